// round 1
// baseline (speedup 1.0000x reference)
#include <cuda_runtime.h>
#include <cuda_bf16.h>

// GNN_84421877170708: 4-layer GCL GNN, fused fp32 implementation with
// packed fma.rn.f32x2 (sm_103a) for 2x fp32 FMA issue throughput.
//
// N=50000 nodes, E=800000 edges, HID=128, EH=64, L=4.

#define N_NODES 50000
#define E_EDGES 800000
#define IN_NF   64
#define HID     128
#define EH      64
#define OUT_NF  64
#define L_LAYERS 4

// Scratch (device globals; no allocation allowed)
__device__ float g_h[N_NODES * HID];    // node state
__device__ float g_agg[N_NODES * EH];   // per-layer message aggregation
__device__ float g_z[N_NODES * HID];    // node-MLP hidden

using u64 = unsigned long long;

__device__ __forceinline__ void ffma2(u64& acc, u64 x, u64 w) {
    asm("fma.rn.f32x2 %0, %1, %2, %0;" : "+l"(acc) : "l"(x), "l"(w));
}
__device__ __forceinline__ u64 pack2(float x) {
    u64 r; asm("mov.b64 %0, {%1, %1};" : "=l"(r) : "f"(x)); return r;
}
__device__ __forceinline__ u64 packf2(float a, float b) {
    u64 r; asm("mov.b64 %0, {%1, %2};" : "=l"(r) : "f"(a), "f"(b)); return r;
}
__device__ __forceinline__ float2 unpack2(u64 v) {
    float2 r; asm("mov.b64 {%0, %1}, %2;" : "=f"(r.x), "=f"(r.y) : "l"(v)); return r;
}
__device__ __forceinline__ float silu(float v) {
    return __fdividef(v, 1.0f + __expf(-v));
}

__device__ __forceinline__ void load_smem(float* dst, const float* __restrict__ src,
                                          int n, int tid, int nthreads) {
    for (int i = tid * 4; i < n; i += nthreads * 4)
        *(float4*)(dst + i) = *(const float4*)(src + i);
}

// ---------------------------------------------------------------------------
// Edge kernel: fused gather -> MLP1(256->64, SiLU) -> MLP2(64->64, SiLU)
//              -> atomic scatter into g_agg[row].
// Per-warp tile: 16 edges. Lane layout: p = lane>>2 (8 output groups of 8),
// q = lane&3 (4 edge groups of 4). Each lane: 4 edges x 8 outputs (as f32x2).
// ---------------------------------------------------------------------------
__global__ void __launch_bounds__(256) edge_kernel(
    const int* __restrict__ edges,
    const float* __restrict__ W1, const float* __restrict__ b1,
    const float* __restrict__ W2, const float* __restrict__ b2)
{
    extern __shared__ float smem[];
    float* w1s = smem;                 // [256][64]
    float* w2s = w1s + 256 * 64;       // [64][64]
    float* b1s = w2s + 64 * 64;        // [64]
    float* b2s = b1s + 64;             // [64]
    float* warpmem = b2s + 64;         // 8 x 3136 floats

    const int tid  = threadIdx.x;
    const int warp = tid >> 5;
    const int lane = tid & 31;

    load_smem(w1s, W1, 256 * 64, tid, 256);
    load_smem(w2s, W2, 64 * 64, tid, 256);
    if (tid < 64) { b1s[tid] = b1[tid]; b2s[tid] = b2[tid]; }
    __syncthreads();

    float* xs   = warpmem + warp * 3136;   // [128][16] staged features
    float* m1s  = xs + 2048;               // [16][66]  MLP1 outputs (padded)
    int*   idxs = (int*)(m1s + 1056);      // [32] rows(0..15), cols(16..31)

    const int p    = lane >> 2;
    const int q    = lane & 3;
    const int m    = lane >> 1;
    const int half = lane & 1;

    u64 bias1[4], bias2[4];
#pragma unroll
    for (int t0 = 0; t0 < 4; t0++) {
        bias1[t0] = packf2(b1s[p * 8 + 2 * t0], b1s[p * 8 + 2 * t0 + 1]);
        bias2[t0] = packf2(b2s[p * 8 + 2 * t0], b2s[p * 8 + 2 * t0 + 1]);
    }

    const int gw     = blockIdx.x * 8 + warp;
    const int nwarps = gridDim.x * 8;
    const int ntiles = E_EDGES / 16;

    for (int t = gw; t < ntiles; t += nwarps) {
        __syncwarp();
        // edge indices for this tile
        if (lane < 16) idxs[lane] = edges[t * 16 + lane];
        else           idxs[lane] = edges[E_EDGES + t * 16 + (lane - 16)];
        __syncwarp();

        u64 acc[4][4];
#pragma unroll
        for (int d = 0; d < 4; d++)
#pragma unroll
            for (int t0 = 0; t0 < 4; t0++) acc[d][t0] = bias1[t0];

        // Two phases: ph=0 -> h[row] (k 0..127), ph=1 -> h[col] (k 128..255)
#pragma unroll 1
        for (int ph = 0; ph < 2; ph++) {
            int node = idxs[ph * 16 + m];
            const float* src = g_h + (long long)node * HID + half * 64;
#pragma unroll
            for (int i = 0; i < 16; i++) {
                float4 v = *(const float4*)(src + i * 4);
                int k = half * 64 + i * 4;
                xs[(k + 0) * 16 + m] = v.x;
                xs[(k + 1) * 16 + m] = v.y;
                xs[(k + 2) * 16 + m] = v.z;
                xs[(k + 3) * 16 + m] = v.w;
            }
            __syncwarp();
            const float* wbase = w1s + ph * 128 * 64;
#pragma unroll 2
            for (int k = 0; k < 128; k++) {
                float4 xv = *(const float4*)&xs[k * 16 + q * 4];
                const ulonglong2* wp = (const ulonglong2*)(wbase + k * 64 + p * 8);
                ulonglong2 wa = wp[0];
                ulonglong2 wb = wp[1];
                u64 xp[4] = {pack2(xv.x), pack2(xv.y), pack2(xv.z), pack2(xv.w)};
#pragma unroll
                for (int d = 0; d < 4; d++) {
                    ffma2(acc[d][0], xp[d], wa.x);
                    ffma2(acc[d][1], xp[d], wa.y);
                    ffma2(acc[d][2], xp[d], wb.x);
                    ffma2(acc[d][3], xp[d], wb.y);
                }
            }
            __syncwarp();
        }

        // SiLU + stage MLP1 result as [edge][66]
#pragma unroll
        for (int d = 0; d < 4; d++) {
            int mm = q * 4 + d;
#pragma unroll
            for (int t0 = 0; t0 < 4; t0++) {
                float2 v = unpack2(acc[d][t0]);
                v.x = silu(v.x);
                v.y = silu(v.y);
                *(float2*)&m1s[mm * 66 + p * 8 + 2 * t0] = v;
            }
        }
        __syncwarp();

        // MLP2: 64 -> 64
        u64 acc2[4][4];
#pragma unroll
        for (int d = 0; d < 4; d++)
#pragma unroll
            for (int t0 = 0; t0 < 4; t0++) acc2[d][t0] = bias2[t0];

#pragma unroll 2
        for (int k = 0; k < 64; k++) {
            float x0 = m1s[(q * 4 + 0) * 66 + k];
            float x1 = m1s[(q * 4 + 1) * 66 + k];
            float x2 = m1s[(q * 4 + 2) * 66 + k];
            float x3 = m1s[(q * 4 + 3) * 66 + k];
            const ulonglong2* wp = (const ulonglong2*)(w2s + k * 64 + p * 8);
            ulonglong2 wa = wp[0];
            ulonglong2 wb = wp[1];
            u64 xp[4] = {pack2(x0), pack2(x1), pack2(x2), pack2(x3)};
#pragma unroll
            for (int d = 0; d < 4; d++) {
                ffma2(acc2[d][0], xp[d], wa.x);
                ffma2(acc2[d][1], xp[d], wa.y);
                ffma2(acc2[d][2], xp[d], wb.x);
                ffma2(acc2[d][3], xp[d], wb.y);
            }
        }

        // SiLU + atomic scatter to g_agg[row]
#pragma unroll
        for (int d = 0; d < 4; d++) {
            int row = idxs[q * 4 + d];
            float* dst = g_agg + (long long)row * EH + p * 8;
#pragma unroll
            for (int t0 = 0; t0 < 4; t0++) {
                float2 v = unpack2(acc2[d][t0]);
                atomicAdd(dst + 2 * t0,     silu(v.x));
                atomicAdd(dst + 2 * t0 + 1, silu(v.y));
            }
        }
    }
}

// ---------------------------------------------------------------------------
// Generic dense layer over nodes: out[n] = act(concat(in1[n], in2[n]) @ W + b)
// Optional SiLU and optional residual (out += existing out).
// Per-warp tile: 16 nodes, lane computes 4 nodes x (NOUT/8) outputs.
// ---------------------------------------------------------------------------
template<int W1IN, int W2IN, int NOUT, bool DO_SILU, bool DO_RES>
__global__ void __launch_bounds__(256) node_gemm(
    const float* __restrict__ in1, const float* __restrict__ in2,
    const float* __restrict__ W, const float* __restrict__ b,
    float* __restrict__ out)
{
    constexpr int KDIM = W1IN + W2IN;
    constexpr int NR   = NOUT / 8;       // outputs per lane
    extern __shared__ float smem[];
    float* ws = smem;                    // [KDIM][NOUT]
    float* bs = ws + KDIM * NOUT;        // [NOUT]
    float* warpmem = bs + NOUT;

    const int tid  = threadIdx.x;
    const int warp = tid >> 5;
    const int lane = tid & 31;

    load_smem(ws, W, KDIM * NOUT, tid, 256);
    if (tid < NOUT) bs[tid] = b[tid];
    __syncthreads();

    float* xs = warpmem + warp * (KDIM * 16);

    const int p    = lane >> 2;
    const int q    = lane & 3;
    const int m    = lane >> 1;
    const int half = lane & 1;

    u64 biasr[NR / 2];
#pragma unroll
    for (int g = 0; g < NR / 2; g++)
        biasr[g] = packf2(bs[p * NR + 2 * g], bs[p * NR + 2 * g + 1]);

    const int gw     = blockIdx.x * 8 + warp;
    const int nwarps = gridDim.x * 8;
    const int ntiles = N_NODES / 16;

    for (int t = gw; t < ntiles; t += nwarps) {
        __syncwarp();
        int node = t * 16 + m;
        const float* s1 = in1 + (long long)node * W1IN;
        const float* s2 = (W2IN > 0) ? in2 + (long long)node * W2IN : nullptr;
#pragma unroll
        for (int i = 0; i < KDIM / 8; i++) {
            int kk = half * (KDIM / 2) + i * 4;
            float4 v;
            if (W2IN == 0 || kk < W1IN) v = *(const float4*)(s1 + kk);
            else                        v = *(const float4*)(s2 + (kk - W1IN));
            xs[(kk + 0) * 16 + m] = v.x;
            xs[(kk + 1) * 16 + m] = v.y;
            xs[(kk + 2) * 16 + m] = v.z;
            xs[(kk + 3) * 16 + m] = v.w;
        }
        __syncwarp();

        u64 acc[4][NR / 2];
#pragma unroll
        for (int d = 0; d < 4; d++)
#pragma unroll
            for (int g = 0; g < NR / 2; g++) acc[d][g] = biasr[g];

#pragma unroll 2
        for (int k = 0; k < KDIM; k++) {
            float4 xv = *(const float4*)&xs[k * 16 + q * 4];
            u64 xp[4] = {pack2(xv.x), pack2(xv.y), pack2(xv.z), pack2(xv.w)};
#pragma unroll
            for (int g = 0; g < NR / 4; g++) {
                ulonglong2 wv = *(const ulonglong2*)(ws + k * NOUT + p * NR + g * 4);
#pragma unroll
                for (int d = 0; d < 4; d++) {
                    ffma2(acc[d][2 * g],     xp[d], wv.x);
                    ffma2(acc[d][2 * g + 1], xp[d], wv.y);
                }
            }
        }

#pragma unroll
        for (int d = 0; d < 4; d++) {
            int nn = t * 16 + q * 4 + d;
            float* dst = out + (long long)nn * NOUT + p * NR;
#pragma unroll
            for (int g = 0; g < NR / 4; g++) {
                float2 a = unpack2(acc[d][2 * g]);
                float2 c = unpack2(acc[d][2 * g + 1]);
                float4 v = make_float4(a.x, a.y, c.x, c.y);
                if (DO_SILU) {
                    v.x = silu(v.x); v.y = silu(v.y);
                    v.z = silu(v.z); v.w = silu(v.w);
                }
                if (DO_RES) {
                    float4 r = *(const float4*)(dst + g * 4);
                    v.x += r.x; v.y += r.y; v.z += r.z; v.w += r.w;
                }
                *(float4*)(dst + g * 4) = v;
            }
        }
    }
}

__global__ void zero_agg_kernel() {
    int i = blockIdx.x * blockDim.x + threadIdx.x;
    if (i < N_NODES * EH / 4)
        ((float4*)g_agg)[i] = make_float4(0.f, 0.f, 0.f, 0.f);
}

extern "C" void kernel_launch(void* const* d_in, const int* in_sizes, int n_in,
                              void* d_out, int out_size)
{
    const float* h_in  = (const float*)d_in[0];
    const int*   edges = (const int*)d_in[1];
    const float* W_in  = (const float*)d_in[2];
    const float* b_in  = (const float*)d_in[3];
    const float* eW1   = (const float*)d_in[4];
    const float* eb1   = (const float*)d_in[5];
    const float* eW2   = (const float*)d_in[6];
    const float* eb2   = (const float*)d_in[7];
    const float* nW1   = (const float*)d_in[8];
    const float* nb1   = (const float*)d_in[9];
    const float* nW2   = (const float*)d_in[10];
    const float* nb2   = (const float*)d_in[11];
    const float* W_out = (const float*)d_in[12];
    const float* b_out = (const float*)d_in[13];

    float* ph;  cudaGetSymbolAddress((void**)&ph,  g_h);
    float* pag; cudaGetSymbolAddress((void**)&pag, g_agg);
    float* pz;  cudaGetSymbolAddress((void**)&pz,  g_z);

    const int smem_edge = (256 * 64 + 64 * 64 + 128 + 8 * 3136) * 4;
    const int smem_na   = ((192 * 128 + 128) + 8 * (192 * 16)) * 4;
    const int smem_nb   = ((128 * 128 + 128) + 8 * (128 * 16)) * 4;
    const int smem_ei   = ((64 * 128 + 128) + 8 * (64 * 16)) * 4;
    const int smem_eo   = ((128 * 64 + 64) + 8 * (128 * 16)) * 4;

    cudaFuncSetAttribute(edge_kernel, cudaFuncAttributeMaxDynamicSharedMemorySize, smem_edge);
    cudaFuncSetAttribute(node_gemm<64, 0, 128, false, false>,
                         cudaFuncAttributeMaxDynamicSharedMemorySize, smem_ei);
    cudaFuncSetAttribute(node_gemm<128, 64, 128, true, false>,
                         cudaFuncAttributeMaxDynamicSharedMemorySize, smem_na);
    cudaFuncSetAttribute(node_gemm<128, 0, 128, false, true>,
                         cudaFuncAttributeMaxDynamicSharedMemorySize, smem_nb);
    cudaFuncSetAttribute(node_gemm<128, 0, 64, false, false>,
                         cudaFuncAttributeMaxDynamicSharedMemorySize, smem_eo);

    // embedding_in: g_h = h @ W_in + b_in
    node_gemm<64, 0, 128, false, false><<<148, 256, smem_ei>>>(
        h_in, nullptr, W_in, b_in, ph);

    for (int l = 0; l < L_LAYERS; l++) {
        zero_agg_kernel<<<(N_NODES * EH / 4 + 255) / 256, 256>>>();
        edge_kernel<<<148, 256, smem_edge>>>(
            edges, eW1 + l * 2 * HID * EH, eb1 + l * EH,
            eW2 + l * EH * EH, eb2 + l * EH);
        // z = silu(concat(h, agg) @ nW1 + nb1)
        node_gemm<128, 64, 128, true, false><<<148, 256, smem_na>>>(
            ph, pag, nW1 + l * (HID + EH) * HID, nb1 + l * HID, pz);
        // h = h + (z @ nW2 + nb2)
        node_gemm<128, 0, 128, false, true><<<148, 256, smem_nb>>>(
            pz, nullptr, nW2 + l * HID * HID, nb2 + l * HID, ph);
    }

    // embedding_out: out = h @ W_out + b_out
    node_gemm<128, 0, 64, false, false><<<148, 256, smem_eo>>>(
        ph, nullptr, W_out, b_out, (float*)d_out);
}